// round 4
// baseline (speedup 1.0000x reference)
#include <cuda_runtime.h>

#define Dm 1024
#define MAXB 8
#define TC 8            // tokens per chunk in k3 (S=2048 -> 256 chunks)
#define MAXCH 256
#define NB 128          // fused-kernel grid; must be <= 148 SMs (all co-resident)

// ---------------- scratch (static device globals) ---------------------------
__device__ float g_q0[MAXB * Dm];              // Wq-GEMV accumulator (init bq)
__device__ float g_u[MAXB * Dm];
__device__ float g_xw[MAXB * Dm];
__device__ float g_r[MAXB * Dm];
__device__ float g_accV[MAXB * Dm];            // Wv-GEMV accumulator (init bv+x0)
__device__ float g_accD[MAXB * Dm];            // Wd-GEMV accumulator (init bd)
__device__ float g_pm[MAXB * MAXCH];
__device__ float g_ps[MAXB * MAXCH];
__device__ float g_pacc[MAXB * MAXCH * Dm];    // 8 MB
__device__ unsigned g_semA1, g_semA2, g_semB1, g_semB2;   // zero-init, self-reset

// ---------------- grid-wide barrier (all NB blocks co-resident) -------------
__device__ __forceinline__ void gsync(volatile unsigned* sem, unsigned target) {
    __syncthreads();
    if (threadIdx.x == 0) {
        __threadfence();
        atomicAdd((unsigned*)sem, 1u);
        while (*sem < target) __nanosleep(32);
        __threadfence();
    }
    __syncthreads();
}

__device__ __forceinline__ void greset(unsigned* sem1, unsigned* sem2) {
    __syncthreads();
    if (threadIdx.x == 0) {
        unsigned v = atomicAdd(sem2, 1u);
        if (v == NB - 1u) { *sem1 = 0u; *sem2 = 0u; __threadfence(); }
    }
}

// ---------------- block reductions ------------------------------------------
__device__ __forceinline__ float blk_reduce(float v, volatile float* sbuf) {
    int lane = threadIdx.x & 31, w = threadIdx.x >> 5;
#pragma unroll
    for (int o = 16; o; o >>= 1) v += __shfl_xor_sync(0xffffffffu, v, o);
    __syncthreads();
    if (lane == 0) sbuf[w] = v;
    __syncthreads();
    int nw = blockDim.x >> 5;
    if (w == 0) {
        float r = (lane < nw) ? sbuf[lane] : 0.f;
#pragma unroll
        for (int o = 16; o; o >>= 1) r += __shfl_xor_sync(0xffffffffu, r, o);
        if (lane == 0) sbuf[0] = r;
    }
    __syncthreads();
    return sbuf[0];
}

__device__ __forceinline__ float blk_rmax(float v, volatile float* sbuf) {
    int lane = threadIdx.x & 31, w = threadIdx.x >> 5;
#pragma unroll
    for (int o = 16; o; o >>= 1) v = fmaxf(v, __shfl_xor_sync(0xffffffffu, v, o));
    __syncthreads();
    if (lane == 0) sbuf[w] = v;
    __syncthreads();
    int nw = blockDim.x >> 5;
    if (w == 0) {
        float r = (lane < nw) ? sbuf[lane] : -1e30f;
#pragma unroll
        for (int o = 16; o; o >>= 1) r = fmaxf(r, __shfl_xor_sync(0xffffffffu, r, o));
        if (lane == 0) sbuf[0] = r;
    }
    __syncthreads();
    return sbuf[0];
}

// ---------------- GEMV phase: atomically accumulate A[b,:]@W into acc -------
// 128 blocks: 4 j-chunks (256 wide) x 32 d-chunks (32 deep). __ldcg for A.
__device__ __forceinline__ void gemv_phase(const float* __restrict__ A, long astride,
                                           const float* __restrict__ W,
                                           float* __restrict__ accout,
                                           int B, float (*as)[32]) {
    int bid = blockIdx.x, tid = threadIdx.x;
    int jc = bid >> 5, dc = bid & 31;
    int j = jc * 256 + tid, d0 = dc * 32;
    {
        int b = tid >> 5, dd = tid & 31;
        as[b][dd] = (b < B) ? __ldcg(&A[(long)b * astride + d0 + dd]) : 0.f;
    }
    __syncthreads();
    float acc[MAXB];
#pragma unroll
    for (int b = 0; b < MAXB; b++) acc[b] = 0.f;
#pragma unroll 8
    for (int dd = 0; dd < 32; dd++) {
        float w = W[(long)(d0 + dd) * Dm + j];
#pragma unroll
        for (int b = 0; b < MAXB; b++) acc[b] = fmaf(as[b][dd], w, acc[b]);
    }
    for (int b = 0; b < B; b++)
        atomicAdd(&accout[(long)b * Dm + j], acc[b]);
}

// ============ kpre: q0 = x0@Wq + bq ; u = Wk @ q0 ===========================
__global__ void __launch_bounds__(256) kpre(const float* __restrict__ x, long xstride,
                                            const float* __restrict__ Wq,
                                            const float* __restrict__ bq,
                                            const float* __restrict__ Wk, int B) {
    __shared__ float as[MAXB][32];
    __shared__ float4 q0s[MAXB * 256];           // 32 KB
    int bid = blockIdx.x, tid = threadIdx.x;

    // P0: init q0 accumulator with bias
    {
        int idx = bid * 256 + tid;
        if (idx < B * Dm) g_q0[idx] = bq[idx & (Dm - 1)];
    }
    gsync(&g_semA1, NB);

    // P1: q0 += x0 @ Wq
    gemv_phase(x, xstride, Wq, g_q0, B, as);
    gsync(&g_semA1, 2u * NB);

    // P2: u[b,d] = Wk[d,:] . q0[b,:]   (warp per row; 128 blocks x 8 warps)
    for (int i = tid; i < MAXB * 256; i += 256)
        q0s[i] = __ldcg(((const float4*)g_q0) + i);
    __syncthreads();
    int wid = tid >> 5, lane = tid & 31;
    int d = bid * 8 + wid;
    const float4* wrow = (const float4*)(Wk + (long)d * Dm);
    float acc[MAXB];
#pragma unroll
    for (int b = 0; b < MAXB; b++) acc[b] = 0.f;
#pragma unroll
    for (int i = 0; i < 8; i++) {
        float4 w = wrow[lane + 32 * i];
#pragma unroll
        for (int b = 0; b < MAXB; b++) {
            float4 q = q0s[b * 256 + lane + 32 * i];
            acc[b] += w.x * q.x + w.y * q.y + w.z * q.z + w.w * q.w;
        }
    }
#pragma unroll
    for (int b = 0; b < MAXB; b++)
#pragma unroll
        for (int o = 16; o; o >>= 1)
            acc[b] += __shfl_xor_sync(0xffffffffu, acc[b], o);
    if (lane == 0)
#pragma unroll
        for (int b = 0; b < MAXB; b++) g_u[(long)b * Dm + d] = acc[b];

    greset(&g_semA1, &g_semA2);
}

// ============ k3: streaming attention, smem-stashed chunk ====================
// grid (S/TC, B), block 256. Phase A: load chunk once from DRAM, dot vs u,
// stash in smem. Phase B: softmax over TC scores. Phase C: weighted sum from smem.
__global__ void __launch_bounds__(256) k3_stream(const float* __restrict__ x,
                                                 const float* __restrict__ u,
                                                 float* __restrict__ pm,
                                                 float* __restrict__ ps,
                                                 float* __restrict__ pacc,
                                                 int S, int nch) {
    int b = blockIdx.y, ch = blockIdx.x;
    int tid = threadIdx.x, wid = tid >> 5, lane = tid & 31;
    __shared__ float4 us[256];                   // 4 KB
    __shared__ float4 chunk[TC][256];            // 32 KB
    __shared__ float sc[TC];
    __shared__ float red[2];

    us[tid] = ((const float4*)(u + (long)b * Dm))[tid];
    __syncthreads();

    // phase A: warp wid owns token t0+wid
    const float4* xr = (const float4*)(x + ((long)b * S + (long)ch * TC + wid) * Dm);
    float dsum = 0.f;
#pragma unroll
    for (int h = 0; h < 2; h++) {
        float4 xv[4];
#pragma unroll
        for (int i = 0; i < 4; i++) xv[i] = xr[lane + 32 * (h * 4 + i)];
#pragma unroll
        for (int i = 0; i < 4; i++) {
            float4 uv = us[lane + 32 * (h * 4 + i)];
            dsum += xv[i].x * uv.x + xv[i].y * uv.y + xv[i].z * uv.z + xv[i].w * uv.w;
            chunk[wid][lane + 32 * (h * 4 + i)] = xv[i];
        }
    }
#pragma unroll
    for (int o = 16; o; o >>= 1) dsum += __shfl_xor_sync(0xffffffffu, dsum, o);
    if (lane == 0) sc[wid] = dsum * 0.03125f;    // 1/sqrt(1024)
    __syncthreads();

    // phase B: softmax over TC=8 scores (single warp)
    if (tid < 32) {
        float v = (tid < TC) ? sc[tid] : -1e30f;
        float m = v;
#pragma unroll
        for (int o = 16; o; o >>= 1) m = fmaxf(m, __shfl_xor_sync(0xffffffffu, m, o));
        float p = __expf(v - m);
        float s = p;
#pragma unroll
        for (int o = 16; o; o >>= 1) s += __shfl_xor_sync(0xffffffffu, s, o);
        if (tid < TC) sc[tid] = p;
        if (tid == 0) { red[0] = m; red[1] = s; }
    }
    __syncthreads();

    // phase C: weighted sum from smem
    float4 a = make_float4(0.f, 0.f, 0.f, 0.f);
#pragma unroll
    for (int t = 0; t < TC; t++) {
        float p = sc[t];
        float4 xv = chunk[t][tid];
        a.x = fmaf(p, xv.x, a.x);
        a.y = fmaf(p, xv.y, a.y);
        a.z = fmaf(p, xv.z, a.z);
        a.w = fmaf(p, xv.w, a.w);
    }
    long ci = (long)b * nch + ch;
    ((float4*)pacc)[ci * 256 + tid] = a;
    if (tid == 0) { pm[ci] = red[0]; ps[ci] = red[1]; }
}

// ============ kpost: merge -> Wv GEMV -> LN1 -> Wd GEMV -> LN2+logits =======
__global__ void __launch_bounds__(256) kpost(const float* __restrict__ x, long xstride,
                                             const float* __restrict__ Wv,
                                             const float* __restrict__ bv,
                                             const float* __restrict__ Wd,
                                             const float* __restrict__ bd,
                                             const float* __restrict__ g1,
                                             const float* __restrict__ b1,
                                             const float* __restrict__ g2,
                                             const float* __restrict__ b2,
                                             const float* __restrict__ Wc,
                                             const float* __restrict__ bc,
                                             float* __restrict__ out,
                                             int B, int nch) {
    __shared__ float f[MAXCH];
    __shared__ float4 partial[16][16];
    __shared__ float sbuf[32];
    __shared__ float as[MAXB][32];
    int bid = blockIdx.x, tid = threadIdx.x;

    // ---- P1: merge chunk partials -> xw; also init accV = bv + x0 ----------
    {
        int b = bid >> 4, jc = bid & 15;
        float v = (tid < nch) ? g_pm[(long)b * nch + tid] : -1e30f;
        float M = blk_rmax(v, sbuf);
        float e = (tid < nch) ? __expf(v - M) : 0.f;
        if (tid < nch) f[tid] = e;
        float s = blk_reduce((tid < nch) ? e * g_ps[(long)b * nch + tid] : 0.f, sbuf);
        float sinv = 1.f / s;

        int jj = tid & 15, cp = tid >> 4;
        int j4 = jc * 16 + jj;
        float4 acc = make_float4(0.f, 0.f, 0.f, 0.f);
        const float4* pa = (const float4*)g_pacc;
        for (int c = cp; c < nch; c += 16) {
            float fc = f[c];
            float4 pv = pa[((long)b * nch + c) * 256 + j4];
            acc.x = fmaf(fc, pv.x, acc.x);
            acc.y = fmaf(fc, pv.y, acc.y);
            acc.z = fmaf(fc, pv.z, acc.z);
            acc.w = fmaf(fc, pv.w, acc.w);
        }
        partial[cp][jj] = acc;
        __syncthreads();
        if (tid < 16) {
            float4 t = partial[0][tid];
#pragma unroll
            for (int p = 1; p < 16; p++) {
                float4 v4 = partial[p][tid];
                t.x += v4.x; t.y += v4.y; t.z += v4.z; t.w += v4.w;
            }
            t.x *= sinv; t.y *= sinv; t.z *= sinv; t.w *= sinv;
            ((float4*)g_xw)[b * 256 + jc * 16 + tid] = t;
        }
        // init accV = bv + x0 (blocks 0..31 cover 8192 elems)
        int idx = bid * 256 + tid;
        if (idx < B * Dm) {
            int bb = idx >> 10, j = idx & (Dm - 1);
            g_accV[idx] = bv[j] + x[(long)bb * xstride + j];
        }
    }
    gsync(&g_semB1, NB);

    // ---- P2: accV += xw @ Wv -----------------------------------------------
    gemv_phase(g_xw, Dm, Wv, g_accV, B, as);
    gsync(&g_semB1, 2u * NB);

    // ---- P3: r = LN1(accV) [blocks 0..B-1]; init accD = bd [blocks 8..39] --
    if (bid < B) {
        int b = bid;
        float vv[4], s1 = 0.f, s2 = 0.f;
#pragma unroll
        for (int k = 0; k < 4; k++) {
            int j = k * 256 + tid;
            float t = __ldcg(&g_accV[(long)b * Dm + j]);
            vv[k] = t; s1 += t; s2 += t * t;
        }
        float sum = blk_reduce(s1, sbuf);
        float sq  = blk_reduce(s2, sbuf);
        float mu  = sum * (1.f / Dm);
        float var = sq * (1.f / Dm) - mu * mu;
        float rstd = rsqrtf(var + 1e-5f);
#pragma unroll
        for (int k = 0; k < 4; k++) {
            int j = k * 256 + tid;
            g_r[(long)b * Dm + j] = (vv[k] - mu) * rstd * g1[j] + b1[j];
        }
    } else if (bid >= MAXB && bid < MAXB + 32) {
        int idx = (bid - MAXB) * 256 + tid;
        if (idx < B * Dm) g_accD[idx] = bd[idx & (Dm - 1)];
    }
    gsync(&g_semB1, 3u * NB);

    // ---- P4: accD += r @ Wd --------------------------------------------------
    gemv_phase(g_r, Dm, Wd, g_accD, B, as);
    gsync(&g_semB1, 4u * NB);

    // ---- P5: h = LN2(relu(accD) + r); logits = h@Wc + bc [blocks 0..B-1] ----
    if (bid < B) {
        int b = bid;
        float vv[4], s1 = 0.f, s2 = 0.f;
#pragma unroll
        for (int k = 0; k < 4; k++) {
            int j = k * 256 + tid;
            float t = __ldcg(&g_accD[(long)b * Dm + j]);
            float rv = __ldcg(&g_r[(long)b * Dm + j]);
            t = fmaxf(t, 0.f) + rv;
            vv[k] = t; s1 += t; s2 += t * t;
        }
        float sum = blk_reduce(s1, sbuf);
        float sq  = blk_reduce(s2, sbuf);
        float mu  = sum * (1.f / Dm);
        float var = sq * (1.f / Dm) - mu * mu;
        float rstd = rsqrtf(var + 1e-5f);
        float l0 = 0.f, l1 = 0.f;
#pragma unroll
        for (int k = 0; k < 4; k++) {
            int j = k * 256 + tid;
            float h = (vv[k] - mu) * rstd * g2[j] + b2[j];
            l0 = fmaf(h, Wc[j * 2 + 0], l0);
            l1 = fmaf(h, Wc[j * 2 + 1], l1);
        }
        l0 = blk_reduce(l0, sbuf);
        l1 = blk_reduce(l1, sbuf);
        if (tid == 0) {
            out[b * 2 + 0] = l0 + bc[0];
            out[b * 2 + 1] = l1 + bc[1];
        }
    }
    greset(&g_semB1, &g_semB2);
}

// ---------------- host --------------------------------------------------------
extern "C" void kernel_launch(void* const* d_in, const int* in_sizes, int n_in,
                              void* d_out, int out_size) {
    const float* x  = (const float*)d_in[0];
    const float* Wq = (const float*)d_in[1];
    const float* bq = (const float*)d_in[2];
    const float* Wk = (const float*)d_in[3];
    // d_in[4] = bk: constant over t in scores -> cancels in softmax; unused.
    const float* Wv = (const float*)d_in[5];
    const float* bv = (const float*)d_in[6];
    const float* Wd = (const float*)d_in[7];
    const float* bd = (const float*)d_in[8];
    const float* g1 = (const float*)d_in[9];
    const float* b1 = (const float*)d_in[10];
    const float* g2 = (const float*)d_in[11];
    const float* b2 = (const float*)d_in[12];
    const float* Wc = (const float*)d_in[13];
    const float* bc = (const float*)d_in[14];
    float* out = (float*)d_out;

    int  B   = out_size / 2;                       // 8
    long xsz = (long)in_sizes[0];
    int  S   = (int)(xsz / ((long)B * Dm));        // 2048
    int  nch = S / TC;                             // 256

    float *u, *pm, *ps, *pacc;
    cudaGetSymbolAddress((void**)&u,    g_u);
    cudaGetSymbolAddress((void**)&pm,   g_pm);
    cudaGetSymbolAddress((void**)&ps,   g_ps);
    cudaGetSymbolAddress((void**)&pacc, g_pacc);

    // q0 = x0@Wq + bq ; u = Wk@q0
    kpre<<<NB, 256>>>(x, (long)S * Dm, Wq, bq, Wk, B);

    // streaming attention partials
    dim3 g3(nch, B);
    k3_stream<<<g3, 256>>>(x, u, pm, ps, pacc, S, nch);

    // merge + Wv + LN1 + Wd + LN2 + logits
    kpost<<<NB, 256>>>(x, (long)S * Dm, Wv, bv, Wd, bd,
                       g1, b1, g2, b2, Wc, bc, out, B, nch);
}

// round 5
// speedup vs baseline: 1.1513x; 1.1513x over previous
#include <cuda_runtime.h>

#define Dm 1024
#define MAXB 8
#define TC 8            // tokens per chunk in k3
#define NCHB 64         // k3 blocks per batch row (persistent, cpb chunks each)
#define DCH 32          // d-chunks for atomic GEMVs

// ---------------- scratch (static device globals) ---------------------------
__device__ float g_q0[MAXB * Dm];              // Wq accumulator (init bq)
__device__ float g_u[MAXB * Dm];
__device__ float g_xw[MAXB * Dm];
__device__ float g_r[MAXB * Dm];
__device__ float g_accV[MAXB * Dm];            // Wv accumulator (init bv + x0)
__device__ float g_accD[MAXB * Dm];            // Wd accumulator (init bd)
__device__ float g_pm[MAXB * NCHB];
__device__ float g_ps[MAXB * NCHB];
__device__ float g_pacc[MAXB * NCHB * Dm];     // 2 MB

// ---------------- block reductions ------------------------------------------
__device__ __forceinline__ float blk_reduce(float v, volatile float* sbuf) {
    int lane = threadIdx.x & 31, w = threadIdx.x >> 5;
#pragma unroll
    for (int o = 16; o; o >>= 1) v += __shfl_xor_sync(0xffffffffu, v, o);
    __syncthreads();
    if (lane == 0) sbuf[w] = v;
    __syncthreads();
    int nw = blockDim.x >> 5;
    if (w == 0) {
        float r = (lane < nw) ? sbuf[lane] : 0.f;
#pragma unroll
        for (int o = 16; o; o >>= 1) r += __shfl_xor_sync(0xffffffffu, r, o);
        if (lane == 0) sbuf[0] = r;
    }
    __syncthreads();
    return sbuf[0];
}

__device__ __forceinline__ float blk_rmax(float v, volatile float* sbuf) {
    int lane = threadIdx.x & 31, w = threadIdx.x >> 5;
#pragma unroll
    for (int o = 16; o; o >>= 1) v = fmaxf(v, __shfl_xor_sync(0xffffffffu, v, o));
    __syncthreads();
    if (lane == 0) sbuf[w] = v;
    __syncthreads();
    int nw = blockDim.x >> 5;
    if (w == 0) {
        float r = (lane < nw) ? sbuf[lane] : -1e30f;
#pragma unroll
        for (int o = 16; o; o >>= 1) r = fmaxf(r, __shfl_xor_sync(0xffffffffu, r, o));
        if (lane == 0) sbuf[0] = r;
    }
    __syncthreads();
    return sbuf[0];
}

// ---------------- kinit: seed the three accumulators -------------------------
__global__ void kinit(const float* __restrict__ x, long xstride,
                      const float* __restrict__ bq,
                      const float* __restrict__ bv,
                      const float* __restrict__ bd, int B) {
    int idx = blockIdx.x * 256 + threadIdx.x;
    int n = B * Dm;
    if (idx < n) {
        int j = idx & (Dm - 1), b = idx >> 10;
        g_q0[idx]   = bq[j];
        g_accV[idx] = bv[j] + x[(long)b * xstride + j];
        g_accD[idx] = bd[j];
    }
}

// ---------------- atomic skinny GEMV: acc[b,j] += A[b,d0:d0+32] @ W ---------
// grid (Dm/256, DCH), block 256
__global__ void gemv_atomic(const float* __restrict__ A, long astride,
                            const float* __restrict__ W,
                            float* __restrict__ accout, int B) {
    __shared__ float as[MAXB][32];
    int j  = blockIdx.x * 256 + threadIdx.x;
    int d0 = blockIdx.y * 32;
    {
        int b = threadIdx.x >> 5, dd = threadIdx.x & 31;
        as[b][dd] = (b < B) ? A[(long)b * astride + d0 + dd] : 0.f;
    }
    __syncthreads();
    float acc[MAXB];
#pragma unroll
    for (int b = 0; b < MAXB; b++) acc[b] = 0.f;
#pragma unroll 8
    for (int dd = 0; dd < 32; dd++) {
        float w = W[(long)(d0 + dd) * Dm + j];
#pragma unroll
        for (int b = 0; b < MAXB; b++) acc[b] = fmaf(as[b][dd], w, acc[b]);
    }
    for (int b = 0; b < B; b++)
        atomicAdd(&accout[(long)b * Dm + j], acc[b]);
}

// ---------------- u[b,d] = Wk[d,:] . q0[b,:]  (8 rows/block) ----------------
__global__ void k2_u(const float* __restrict__ Wk,
                     const float* __restrict__ q0,
                     float* __restrict__ u) {
    __shared__ float4 q0s[MAXB * 256];               // 32 KB
    for (int i = threadIdx.x; i < MAXB * 256; i += 256)
        q0s[i] = ((const float4*)q0)[i];
    __syncthreads();
    int wid = threadIdx.x >> 5, lane = threadIdx.x & 31;
    int d = blockIdx.x * 8 + wid;
    const float4* wrow = (const float4*)(Wk + (long)d * Dm);
    float acc[MAXB];
#pragma unroll
    for (int b = 0; b < MAXB; b++) acc[b] = 0.f;
#pragma unroll
    for (int i = 0; i < 8; i++) {
        float4 w = wrow[lane + 32 * i];
#pragma unroll
        for (int b = 0; b < MAXB; b++) {
            float4 q = q0s[b * 256 + lane + 32 * i];
            acc[b] += w.x * q.x + w.y * q.y + w.z * q.z + w.w * q.w;
        }
    }
#pragma unroll
    for (int b = 0; b < MAXB; b++)
#pragma unroll
        for (int o = 16; o; o >>= 1)
            acc[b] += __shfl_xor_sync(0xffffffffu, acc[b], o);
    if (lane == 0)
#pragma unroll
        for (int b = 0; b < MAXB; b++) u[(long)b * Dm + d] = acc[b];
}

// ---------------- k3: persistent pipelined streaming (cp.async) -------------
// grid (NCHB, B), 256 thr, dyn smem: us(4K) + 2 chunk bufs (32K each) + sc/red.
// Each block: cpb chunks of TC=8 tokens, online softmax, one partial out.
__global__ void __launch_bounds__(256) k3_pipe(const float* __restrict__ x,
                                               const float* __restrict__ u,
                                               float* __restrict__ pm,
                                               float* __restrict__ ps,
                                               float* __restrict__ pacc,
                                               int S, int cpb) {
    extern __shared__ float4 dynsm[];
    float4* us   = dynsm;                  // 256
    float4* buf0 = dynsm + 256;            // TC*256
    float4* buf1 = buf0 + TC * 256;        // TC*256
    float*  sc   = (float*)(buf1 + TC * 256);   // TC
    float*  red  = sc + TC;                     // 1

    int b = blockIdx.y, blk = blockIdx.x;
    int tid = threadIdx.x, wid = tid >> 5, lane = tid & 31;

    us[tid] = ((const float4*)(u + (long)b * Dm))[tid];

    const float4* xg = (const float4*)x + ((long)b * S + (long)blk * cpb * TC) * 256;

    // prefill 2 chunks (always commit 2 groups)
#pragma unroll
    for (int c0 = 0; c0 < 2; c0++) {
        if (c0 < cpb) {
            float4* dst = c0 ? buf1 : buf0;
            const float4* src = xg + (long)c0 * TC * 256;
#pragma unroll
            for (int i = 0; i < TC; i++) {
                unsigned sa = (unsigned)__cvta_generic_to_shared(dst + i * 256 + tid);
                asm volatile("cp.async.cg.shared.global [%0], [%1], 16;\n"
                             :: "r"(sa), "l"(src + i * 256 + tid));
            }
        }
        asm volatile("cp.async.commit_group;\n");
    }

    float m_run = -1e30f, s_run = 0.f;     // maintained by warp 0
    float4 acc = make_float4(0.f, 0.f, 0.f, 0.f);

    for (int c = 0; c < cpb; c++) {
        asm volatile("cp.async.wait_group 1;\n");
        __syncthreads();
        float4* bufc = (c & 1) ? buf1 : buf0;

        // dots: warp wid -> token wid
        float d = 0.f;
#pragma unroll
        for (int i = 0; i < 8; i++) {
            float4 xv = bufc[wid * 256 + lane + 32 * i];
            float4 uv = us[lane + 32 * i];
            d += xv.x * uv.x + xv.y * uv.y + xv.z * uv.z + xv.w * uv.w;
        }
#pragma unroll
        for (int o = 16; o; o >>= 1) d += __shfl_xor_sync(0xffffffffu, d, o);
        if (lane == 0) sc[wid] = d * 0.03125f;       // 1/sqrt(1024)
        __syncthreads();

        // online softmax update (warp 0)
        if (tid < 32) {
            float v = (tid < TC) ? sc[tid] : -1e30f;
            float mc = v;
#pragma unroll
            for (int o = 16; o; o >>= 1) mc = fmaxf(mc, __shfl_xor_sync(0xffffffffu, mc, o));
            float mn = fmaxf(m_run, mc);
            float cc = __expf(m_run - mn);
            float p  = __expf(v - mn);
            float ss = p;
#pragma unroll
            for (int o = 16; o; o >>= 1) ss += __shfl_xor_sync(0xffffffffu, ss, o);
            s_run = s_run * cc + ss;
            m_run = mn;
            if (tid < TC) sc[tid] = p;
            if (tid == 0) red[0] = cc;
        }
        __syncthreads();

        // rescale + accumulate from smem
        float cc = red[0];
        acc.x *= cc; acc.y *= cc; acc.z *= cc; acc.w *= cc;
#pragma unroll
        for (int t = 0; t < TC; t++) {
            float p = sc[t];
            float4 xv = bufc[t * 256 + tid];
            acc.x = fmaf(p, xv.x, acc.x);
            acc.y = fmaf(p, xv.y, acc.y);
            acc.z = fmaf(p, xv.z, acc.z);
            acc.w = fmaf(p, xv.w, acc.w);
        }
        __syncthreads();                              // done reading bufc

        // refill bufc with chunk c+2
        if (c + 2 < cpb) {
            const float4* src = xg + (long)(c + 2) * TC * 256;
#pragma unroll
            for (int i = 0; i < TC; i++) {
                unsigned sa = (unsigned)__cvta_generic_to_shared(bufc + i * 256 + tid);
                asm volatile("cp.async.cg.shared.global [%0], [%1], 16;\n"
                             :: "r"(sa), "l"(src + i * 256 + tid));
            }
        }
        asm volatile("cp.async.commit_group;\n");
    }

    long ci = (long)b * NCHB + blk;
    ((float4*)pacc)[ci * 256 + tid] = acc;
    if (tid == 0) { pm[ci] = m_run; ps[ci] = s_run; }
}

// ---------------- merge block partials -> xw[b,:] ---------------------------
// grid (B, 16), 128 thr; nch = NCHB = 64 partials per b.
__global__ void k4a_merge(const float* __restrict__ pm,
                          const float* __restrict__ ps,
                          const float* __restrict__ pacc,
                          float* __restrict__ xw, int nch) {
    int b = blockIdx.x, jc = blockIdx.y;
    int tid = threadIdx.x;
    __shared__ float f[NCHB];
    __shared__ float4 partial[8][16];
    __shared__ float sbuf[32];

    float v = (tid < nch) ? pm[(long)b * nch + tid] : -1e30f;
    float M = blk_rmax(v, sbuf);
    float e = (tid < nch) ? __expf(v - M) : 0.f;
    if (tid < nch) f[tid] = e;
    float s = blk_reduce((tid < nch) ? e * ps[(long)b * nch + tid] : 0.f, sbuf);
    float sinv = 1.f / s;

    int jj = tid & 15, cp = tid >> 4;                 // 16 j4 x 8 partitions
    int j4 = jc * 16 + jj;
    const float4* pa = (const float4*)pacc;
    float4 acc = make_float4(0.f, 0.f, 0.f, 0.f);
    for (int c = cp; c < nch; c += 8) {
        float fc = f[c];
        float4 pv = pa[((long)b * nch + c) * 256 + j4];
        acc.x = fmaf(fc, pv.x, acc.x);
        acc.y = fmaf(fc, pv.y, acc.y);
        acc.z = fmaf(fc, pv.z, acc.z);
        acc.w = fmaf(fc, pv.w, acc.w);
    }
    partial[cp][jj] = acc;
    __syncthreads();
    if (tid < 16) {
        float4 t = partial[0][tid];
#pragma unroll
        for (int p = 1; p < 8; p++) {
            float4 v4 = partial[p][tid];
            t.x += v4.x; t.y += v4.y; t.z += v4.z; t.w += v4.w;
        }
        t.x *= sinv; t.y *= sinv; t.z *= sinv; t.w *= sinv;
        ((float4*)xw)[b * 256 + jc * 16 + tid] = t;
    }
}

// ---------------- r = LN1(accV) ----------------------------------------------
__global__ void __launch_bounds__(1024) k_ln1(const float* __restrict__ acc,
                                              const float* __restrict__ g1,
                                              const float* __restrict__ b1,
                                              float* __restrict__ r) {
    int b = blockIdx.x, j = threadIdx.x;
    __shared__ float sbuf[32];
    float v = acc[(long)b * Dm + j];
    float sum = blk_reduce(v, sbuf);
    float sq  = blk_reduce(v * v, sbuf);
    float mu  = sum * (1.f / Dm);
    float var = sq * (1.f / Dm) - mu * mu;
    float rstd = rsqrtf(var + 1e-5f);
    r[(long)b * Dm + j] = (v - mu) * rstd * g1[j] + b1[j];
}

// ---------------- h = LN2(relu(accD) + r); logits = h@Wc + bc ----------------
__global__ void __launch_bounds__(1024) k_ln2(const float* __restrict__ acc,
                                              const float* __restrict__ r,
                                              const float* __restrict__ g2,
                                              const float* __restrict__ b2,
                                              const float* __restrict__ Wc,
                                              const float* __restrict__ bc,
                                              float* __restrict__ out) {
    int b = blockIdx.x, j = threadIdx.x;
    __shared__ float sbuf[32];
    float v = fmaxf(acc[(long)b * Dm + j], 0.f) + r[(long)b * Dm + j];
    float sum = blk_reduce(v, sbuf);
    float sq  = blk_reduce(v * v, sbuf);
    float mu  = sum * (1.f / Dm);
    float var = sq * (1.f / Dm) - mu * mu;
    float rstd = rsqrtf(var + 1e-5f);
    float h = (v - mu) * rstd * g2[j] + b2[j];
    float l0 = blk_reduce(h * Wc[j * 2 + 0], sbuf);
    float l1 = blk_reduce(h * Wc[j * 2 + 1], sbuf);
    if (j == 0) {
        out[b * 2 + 0] = l0 + bc[0];
        out[b * 2 + 1] = l1 + bc[1];
    }
}

// ---------------- host --------------------------------------------------------
extern "C" void kernel_launch(void* const* d_in, const int* in_sizes, int n_in,
                              void* d_out, int out_size) {
    const float* x  = (const float*)d_in[0];
    const float* Wq = (const float*)d_in[1];
    const float* bq = (const float*)d_in[2];
    const float* Wk = (const float*)d_in[3];
    // d_in[4] = bk: constant over t in scores -> cancels in softmax; unused.
    const float* Wv = (const float*)d_in[5];
    const float* bv = (const float*)d_in[6];
    const float* Wd = (const float*)d_in[7];
    const float* bd = (const float*)d_in[8];
    const float* g1 = (const float*)d_in[9];
    const float* b1 = (const float*)d_in[10];
    const float* g2 = (const float*)d_in[11];
    const float* b2 = (const float*)d_in[12];
    const float* Wc = (const float*)d_in[13];
    const float* bc = (const float*)d_in[14];
    float* out = (float*)d_out;

    int  B   = out_size / 2;                       // 8
    long xsz = (long)in_sizes[0];
    int  S   = (int)(xsz / ((long)B * Dm));        // 2048
    int  nch = S / TC;                             // 256
    int  cpb = nch / NCHB;                         // 4

    float *q0, *u, *xw, *r, *accV, *accD, *pm, *ps, *pacc;
    cudaGetSymbolAddress((void**)&q0,   g_q0);
    cudaGetSymbolAddress((void**)&u,    g_u);
    cudaGetSymbolAddress((void**)&xw,   g_xw);
    cudaGetSymbolAddress((void**)&r,    g_r);
    cudaGetSymbolAddress((void**)&accV, g_accV);
    cudaGetSymbolAddress((void**)&accD, g_accD);
    cudaGetSymbolAddress((void**)&pm,   g_pm);
    cudaGetSymbolAddress((void**)&ps,   g_ps);
    cudaGetSymbolAddress((void**)&pacc, g_pacc);

    static int smem_set = 0;
    int smem_bytes = (256 + 2 * TC * 256) * 16 + (TC + 1) * 4;   // ~69700
    if (!smem_set) {
        cudaFuncSetAttribute(k3_pipe, cudaFuncAttributeMaxDynamicSharedMemorySize,
                             smem_bytes);
        smem_set = 1;
    }

    // seed accumulators: q0=bq, accV=bv+x0, accD=bd
    kinit<<<(3 * B * Dm + 255) / 256, 256>>>(x, (long)S * Dm, bq, bv, bd, B);

    // q0 += x0 @ Wq
    dim3 gp(Dm / 256, DCH);
    gemv_atomic<<<gp, 256>>>(x, (long)S * Dm, Wq, q0, B);

    // u = Wk @ q0
    k2_u<<<Dm / 8, 256>>>(Wk, q0, u);

    // streaming attention partials (pipelined, persistent)
    dim3 g3(NCHB, B);
    k3_pipe<<<g3, 256, smem_bytes>>>(x, u, pm, ps, pacc, S, cpb);

    // merge -> xw
    dim3 gm(B, 16);
    k4a_merge<<<gm, 128>>>(pm, ps, pacc, xw, NCHB);

    // accV += xw @ Wv ; r = LN1(accV)
    gemv_atomic<<<gp, 256>>>(xw, (long)Dm, Wv, accV, B);
    k_ln1<<<B, 1024>>>(accV, g1, b1, r);

    // accD += r @ Wd ; out = LN2(relu(accD)+r) @ Wc + bc
    gemv_atomic<<<gp, 256>>>(r, (long)Dm, Wd, accD, B);
    k_ln2<<<B, 1024>>>(accD, r, g2, b2, Wc, bc, out);
}

// round 7
// speedup vs baseline: 1.6721x; 1.4524x over previous
#include <cuda_runtime.h>

#define Dm 1024
#define MAXB 8
#define SMAX 4096

// ---------------- scratch (static device globals) ---------------------------
__device__ float g_q0[MAXB * Dm];              // Wq accumulator (init bq)
__device__ float g_u[MAXB * Dm];
__device__ float g_xw[MAXB * Dm];              // k3b accumulator (init 0)
__device__ float g_r[MAXB * Dm];
__device__ float g_accV[MAXB * Dm];            // Wv accumulator (init bv + x0)
__device__ float g_accD[MAXB * Dm];            // Wd accumulator (init bd)
__device__ float g_sc[MAXB * SMAX];            // attention scores

// ---------------- block reductions ------------------------------------------
__device__ __forceinline__ float blk_reduce(float v, volatile float* sbuf) {
    int lane = threadIdx.x & 31, w = threadIdx.x >> 5;
#pragma unroll
    for (int o = 16; o; o >>= 1) v += __shfl_xor_sync(0xffffffffu, v, o);
    __syncthreads();
    if (lane == 0) sbuf[w] = v;
    __syncthreads();
    int nw = blockDim.x >> 5;
    if (w == 0) {
        float r = (lane < nw) ? sbuf[lane] : 0.f;
#pragma unroll
        for (int o = 16; o; o >>= 1) r += __shfl_xor_sync(0xffffffffu, r, o);
        if (lane == 0) sbuf[0] = r;
    }
    __syncthreads();
    return sbuf[0];
}

__device__ __forceinline__ float blk_rmax(float v, volatile float* sbuf) {
    int lane = threadIdx.x & 31, w = threadIdx.x >> 5;
#pragma unroll
    for (int o = 16; o; o >>= 1) v = fmaxf(v, __shfl_xor_sync(0xffffffffu, v, o));
    __syncthreads();
    if (lane == 0) sbuf[w] = v;
    __syncthreads();
    int nw = blockDim.x >> 5;
    if (w == 0) {
        float r = (lane < nw) ? sbuf[lane] : -1e30f;
#pragma unroll
        for (int o = 16; o; o >>= 1) r = fmaxf(r, __shfl_xor_sync(0xffffffffu, r, o));
        if (lane == 0) sbuf[0] = r;
    }
    __syncthreads();
    return sbuf[0];
}

// ---------------- kinit: seed accumulators -----------------------------------
__global__ void kinit(const float* __restrict__ x, long xstride,
                      const float* __restrict__ bq,
                      const float* __restrict__ bv,
                      const float* __restrict__ bd, int B) {
    int idx = blockIdx.x * 256 + threadIdx.x;
    if (idx < B * Dm) {
        int j = idx & (Dm - 1), b = idx >> 10;
        g_q0[idx]   = bq[j];
        g_accV[idx] = bv[j] + x[(long)b * xstride + j];
        g_accD[idx] = bd[j];
        g_xw[idx]   = 0.f;
    }
}

// ---------------- PDL skinny GEMV: acc[b,j] += A[b,d0:d0+32] @ W -------------
// grid (4, 32), block 256. W tile preloaded to regs BEFORE gridsync (overlap).
__global__ void __launch_bounds__(256) gemv_pdl(const float* __restrict__ A,
                                                long astride,
                                                const float* __restrict__ W,
                                                float* __restrict__ accout, int B) {
    __shared__ float as[MAXB][32];
    int j  = blockIdx.x * 256 + threadIdx.x;
    int d0 = blockIdx.y * 32;
    float wv[32];
#pragma unroll
    for (int dd = 0; dd < 32; dd++) wv[dd] = W[(long)(d0 + dd) * Dm + j];
    cudaGridDependencySynchronize();
    {
        int b = threadIdx.x >> 5, dd = threadIdx.x & 31;
        as[b][dd] = (b < B) ? A[(long)b * astride + d0 + dd] : 0.f;
    }
    __syncthreads();
    float acc[MAXB];
#pragma unroll
    for (int b = 0; b < MAXB; b++) acc[b] = 0.f;
#pragma unroll
    for (int dd = 0; dd < 32; dd++) {
#pragma unroll
        for (int b = 0; b < MAXB; b++) acc[b] = fmaf(as[b][dd], wv[dd], acc[b]);
    }
    for (int b = 0; b < B; b++)
        atomicAdd(&accout[(long)b * Dm + j], acc[b]);
}

// ---------------- u[b,d] = Wk[d,:] . q0[b,:] ---------------------------------
// 128 blocks x 8 warps (1 row each). Wk row preloaded to regs before gridsync.
__global__ void __launch_bounds__(256) k2_u(const float* __restrict__ Wk,
                                            const float* __restrict__ q0g,
                                            float* __restrict__ u) {
    __shared__ float4 q0s[MAXB * 256];               // 32 KB
    int wid = threadIdx.x >> 5, lane = threadIdx.x & 31;
    int d = blockIdx.x * 8 + wid;
    const float4* wrow = (const float4*)(Wk + (long)d * Dm);
    float4 wv[8];
#pragma unroll
    for (int i = 0; i < 8; i++) wv[i] = wrow[lane + 32 * i];
    cudaGridDependencySynchronize();
    for (int i = threadIdx.x; i < MAXB * 256; i += 256)
        q0s[i] = ((const float4*)q0g)[i];
    __syncthreads();
    float acc[MAXB];
#pragma unroll
    for (int b = 0; b < MAXB; b++) acc[b] = 0.f;
#pragma unroll
    for (int i = 0; i < 8; i++) {
#pragma unroll
        for (int b = 0; b < MAXB; b++) {
            float4 q = q0s[b * 256 + lane + 32 * i];
            acc[b] += wv[i].x * q.x + wv[i].y * q.y + wv[i].z * q.z + wv[i].w * q.w;
        }
    }
#pragma unroll
    for (int b = 0; b < MAXB; b++)
#pragma unroll
        for (int o = 16; o; o >>= 1)
            acc[b] += __shfl_xor_sync(0xffffffffu, acc[b], o);
    if (lane == 0)
#pragma unroll
        for (int b = 0; b < MAXB; b++) u[(long)b * Dm + d] = acc[b];
}

// ---------------- k3a: pure score stream -------------------------------------
// grid (S/32, B), 256 thr: 8 warps x 4 tokens. u in registers, zero smem for x.
__global__ void __launch_bounds__(256) k3a(const float* __restrict__ x,
                                           const float* __restrict__ ug,
                                           float* __restrict__ sc, int S) {
    int b = blockIdx.y;
    int wid = threadIdx.x >> 5, lane = threadIdx.x & 31;
    int tbase = blockIdx.x * 32 + wid * 4;
    const float4* x0 = (const float4*)x + ((long)b * S + tbase) * 256;
#pragma unroll
    for (int i = 0; i < 8; i++)
        asm volatile("prefetch.global.L2 [%0];" :: "l"(x0 + lane + 32 * i));
    cudaGridDependencySynchronize();
    const float4* ub = (const float4*)(ug + (long)b * Dm);
    float4 uv[8];
#pragma unroll
    for (int i = 0; i < 8; i++) uv[i] = __ldg(ub + lane + 32 * i);
#pragma unroll
    for (int k = 0; k < 4; k++) {
        const float4* xr = x0 + (long)k * 256;
        float d = 0.f;
#pragma unroll
        for (int i = 0; i < 8; i++) {
            float4 xv = xr[lane + 32 * i];
            d += xv.x * uv[i].x + xv.y * uv[i].y + xv.z * uv[i].z + xv.w * uv[i].w;
        }
#pragma unroll
        for (int o = 16; o; o >>= 1) d += __shfl_xor_sync(0xffffffffu, d, o);
        if (lane == 0) sc[(long)b * S + tbase + k] = d * 0.03125f;  // 1/sqrt(1024)
    }
}

// ---------------- k3b: softmax (redundant per block) + weighted accumulate --
// grid ((S/128)*4, B), 256 thr. x re-read from L2. atomicAdd into xw.
__global__ void __launch_bounds__(256) k3b(const float* __restrict__ x,
                                           const float* __restrict__ scg,
                                           float* __restrict__ xw, int S) {
    __shared__ float w[128];
    __shared__ float sbuf[32];
    __shared__ float4 redb[4][64];
    int b = blockIdx.y;
    int ntc = S >> 7;                                 // 128-token chunks
    int tc = blockIdx.x % ntc, jc = blockIdx.x / ntc; // jc in 0..3
    int tid = threadIdx.x;
    cudaGridDependencySynchronize();

    const float* sb = scg + (long)b * S;
    float m = -1e30f;
    for (int t = tid; t < S; t += 256) m = fmaxf(m, sb[t]);
    m = blk_rmax(m, sbuf);
    float s = 0.f;
    for (int t = tid; t < S; t += 256) s += __expf(sb[t] - m);
    s = blk_reduce(s, sbuf);
    float zinv = 1.f / s;
    if (tid < 128) w[tid] = __expf(sb[tc * 128 + tid] - m) * zinv;
    __syncthreads();

    int tg = tid >> 6, jj = tid & 63;
    int j4 = jc * 64 + jj;
    const float4* xb = (const float4*)x + ((long)b * S + tc * 128) * 256;
    float4 acc = make_float4(0.f, 0.f, 0.f, 0.f);
#pragma unroll 8
    for (int t = tg; t < 128; t += 4) {
        float p = w[t];
        float4 xv = xb[(long)t * 256 + j4];
        acc.x = fmaf(p, xv.x, acc.x);
        acc.y = fmaf(p, xv.y, acc.y);
        acc.z = fmaf(p, xv.z, acc.z);
        acc.w = fmaf(p, xv.w, acc.w);
    }
    redb[tg][jj] = acc;
    __syncthreads();
    if (tg == 0) {
        float4 t0 = redb[0][jj];
#pragma unroll
        for (int p = 1; p < 4; p++) {
            float4 v = redb[p][jj];
            t0.x += v.x; t0.y += v.y; t0.z += v.z; t0.w += v.w;
        }
        float* dst = &xw[(long)b * Dm + j4 * 4];
        atomicAdd(dst + 0, t0.x);
        atomicAdd(dst + 1, t0.y);
        atomicAdd(dst + 2, t0.z);
        atomicAdd(dst + 3, t0.w);
    }
}

// ---------------- r = LN1(accV) ----------------------------------------------
__global__ void __launch_bounds__(1024) k_ln1(const float* __restrict__ acc,
                                              const float* __restrict__ g1,
                                              const float* __restrict__ b1,
                                              float* __restrict__ r) {
    int b = blockIdx.x, j = threadIdx.x;
    __shared__ float sbuf[32];
    float gg = g1[j], bb = b1[j];
    cudaGridDependencySynchronize();
    float v = acc[(long)b * Dm + j];
    float sum = blk_reduce(v, sbuf);
    float sq  = blk_reduce(v * v, sbuf);
    float mu  = sum * (1.f / Dm);
    float var = sq * (1.f / Dm) - mu * mu;
    float rstd = rsqrtf(var + 1e-5f);
    r[(long)b * Dm + j] = (v - mu) * rstd * gg + bb;
}

// ---------------- h = LN2(relu(accD) + r); logits = h@Wc + bc ----------------
__global__ void __launch_bounds__(1024) k_ln2(const float* __restrict__ acc,
                                              const float* __restrict__ r,
                                              const float* __restrict__ g2,
                                              const float* __restrict__ b2,
                                              const float* __restrict__ Wc,
                                              const float* __restrict__ bc,
                                              float* __restrict__ out) {
    int b = blockIdx.x, j = threadIdx.x;
    __shared__ float sbuf[32];
    float gg = g2[j], bb = b2[j];
    float w0 = Wc[j * 2 + 0], w1 = Wc[j * 2 + 1];
    cudaGridDependencySynchronize();
    float v = fmaxf(acc[(long)b * Dm + j], 0.f) + r[(long)b * Dm + j];
    float sum = blk_reduce(v, sbuf);
    float sq  = blk_reduce(v * v, sbuf);
    float mu  = sum * (1.f / Dm);
    float var = sq * (1.f / Dm) - mu * mu;
    float rstd = rsqrtf(var + 1e-5f);
    float h = (v - mu) * rstd * gg + bb;
    float l0 = blk_reduce(h * w0, sbuf);
    float l1 = blk_reduce(h * w1, sbuf);
    if (j == 0) {
        out[b * 2 + 0] = l0 + bc[0];
        out[b * 2 + 1] = l1 + bc[1];
    }
}

// ---------------- host --------------------------------------------------------
static void launch_ex(const void* fn, dim3 grid, dim3 block, void** args, bool pdl) {
    cudaLaunchConfig_t cfg = {};
    cfg.gridDim = grid;
    cfg.blockDim = block;
    cfg.dynamicSmemBytes = 0;
    cfg.stream = 0;
    cudaLaunchAttribute attr[1];
    attr[0].id = cudaLaunchAttributeProgrammaticStreamSerialization;
    attr[0].val.programmaticStreamSerializationAllowed = 1;
    cfg.attrs = attr;
    cfg.numAttrs = pdl ? 1 : 0;
    cudaLaunchKernelExC(&cfg, fn, args);
}

extern "C" void kernel_launch(void* const* d_in, const int* in_sizes, int n_in,
                              void* d_out, int out_size) {
    const float* x  = (const float*)d_in[0];
    const float* Wq = (const float*)d_in[1];
    const float* bq = (const float*)d_in[2];
    const float* Wk = (const float*)d_in[3];
    // d_in[4] = bk: constant over t in scores -> cancels in softmax; unused.
    const float* Wv = (const float*)d_in[5];
    const float* bv = (const float*)d_in[6];
    const float* Wd = (const float*)d_in[7];
    const float* bd = (const float*)d_in[8];
    const float* g1 = (const float*)d_in[9];
    const float* b1 = (const float*)d_in[10];
    const float* g2 = (const float*)d_in[11];
    const float* b2 = (const float*)d_in[12];
    const float* Wc = (const float*)d_in[13];
    const float* bc = (const float*)d_in[14];
    float* out = (float*)d_out;

    int  B   = out_size / 2;                       // 8
    long xsz = (long)in_sizes[0];
    int  S   = (int)(xsz / ((long)B * Dm));        // 2048
    long xstride = (long)S * Dm;

    float *q0, *u, *xw, *r, *accV, *accD, *sc;
    cudaGetSymbolAddress((void**)&q0,   g_q0);
    cudaGetSymbolAddress((void**)&u,    g_u);
    cudaGetSymbolAddress((void**)&xw,   g_xw);
    cudaGetSymbolAddress((void**)&r,    g_r);
    cudaGetSymbolAddress((void**)&accV, g_accV);
    cudaGetSymbolAddress((void**)&accD, g_accD);
    cudaGetSymbolAddress((void**)&sc,   g_sc);

    // 1. seed accumulators (no early trigger anywhere: implicit trigger at
    //    grid completion guarantees memory visibility; downstream preambles
    //    still overlap upstream execution)
    {
        void* a[] = {(void*)&x, (void*)&xstride, (void*)&bq, (void*)&bv, (void*)&bd, (void*)&B};
        launch_ex((const void*)kinit, dim3((B * Dm + 255) / 256), dim3(256), a, false);
    }
    // 2. q0 += x0 @ Wq
    {
        void* a[] = {(void*)&x, (void*)&xstride, (void*)&Wq, (void*)&q0, (void*)&B};
        launch_ex((const void*)gemv_pdl, dim3(4, 32), dim3(256), a, true);
    }
    // 3. u = Wk @ q0
    {
        void* a[] = {(void*)&Wk, (void*)&q0, (void*)&u};
        launch_ex((const void*)k2_u, dim3(Dm / 8), dim3(256), a, true);
    }
    // 4. scores
    {
        void* a[] = {(void*)&x, (void*)&u, (void*)&sc, (void*)&S};
        launch_ex((const void*)k3a, dim3(S / 32, B), dim3(256), a, true);
    }
    // 5. softmax + weighted accumulate -> xw
    {
        void* a[] = {(void*)&x, (void*)&sc, (void*)&xw, (void*)&S};
        launch_ex((const void*)k3b, dim3((S / 128) * 4, B), dim3(256), a, true);
    }
    // 6. accV += xw @ Wv
    {
        long st = Dm;
        void* a[] = {(void*)&xw, (void*)&st, (void*)&Wv, (void*)&accV, (void*)&B};
        launch_ex((const void*)gemv_pdl, dim3(4, 32), dim3(256), a, true);
    }
    // 7. r = LN1(accV)
    {
        void* a[] = {(void*)&accV, (void*)&g1, (void*)&b1, (void*)&r};
        launch_ex((const void*)k_ln1, dim3(B), dim3(1024), a, true);
    }
    // 8. accD += r @ Wd
    {
        long st = Dm;
        void* a[] = {(void*)&r, (void*)&st, (void*)&Wd, (void*)&accD, (void*)&B};
        launch_ex((const void*)gemv_pdl, dim3(4, 32), dim3(256), a, true);
    }
    // 9. out = LN2(relu(accD)+r) @ Wc + bc
    {
        void* a[] = {(void*)&accD, (void*)&r, (void*)&g2, (void*)&b2,
                     (void*)&Wc, (void*)&bc, (void*)&out};
        launch_ex((const void*)k_ln2, dim3(B), dim3(1024), a, true);
    }
}